// round 10
// baseline (speedup 1.0000x reference)
#include <cuda_runtime.h>
#include <cuda_bf16.h>

#define NDIM 64
#define MAXN 100000
#define MAXE 3200000
#define NREL 32
#define CAP 128          // padded bucket capacity per row (degree ~Poisson(32))
#define RPW 8            // rows per warp batch

// ---------------- device scratch (no allocations allowed; zero-initialized) ----------------
__device__ int g_cnt[MAXN];
__device__ float g_w[MAXN * NREL];                       // per-(node, rel) weights
__device__ unsigned long long g_es[(size_t)MAXN * CAP];  // padded buckets: (col, val)

// ---------------- packed f32x2 helpers (sm_103a) ----------------
__device__ __forceinline__ unsigned long long pk2f(float lo, float hi) {
    unsigned long long r;
    asm("mov.b64 %0, {%1, %2};" : "=l"(r) : "r"(__float_as_uint(lo)), "r"(__float_as_uint(hi)));
    return r;
}
__device__ __forceinline__ unsigned long long pk2u(unsigned lo, unsigned hi) {
    unsigned long long r;
    asm("mov.b64 %0, {%1, %2};" : "=l"(r) : "r"(lo), "r"(hi));
    return r;
}
__device__ __forceinline__ void up2(float& lo, float& hi, unsigned long long v) {
    unsigned a, b;
    asm("mov.b64 {%0, %1}, %2;" : "=r"(a), "=r"(b) : "l"(v));
    lo = __uint_as_float(a); hi = __uint_as_float(b);
}
__device__ __forceinline__ void fma2(unsigned long long& d, unsigned long long a,
                                     unsigned long long b, unsigned long long c) {
    asm("fma.rn.f32x2 %0, %1, %2, %3;" : "=l"(d) : "l"(a), "l"(b), "l"(c));
}
__device__ __forceinline__ void add2(unsigned long long& d, unsigned long long a,
                                     unsigned long long b) {
    asm("add.rn.f32x2 %0, %1, %2;" : "=l"(d) : "l"(a), "l"(b));
}
__device__ __forceinline__ void mul2(unsigned long long& d, unsigned long long a,
                                     unsigned long long b) {
    asm("mul.rn.f32x2 %0, %1, %2;" : "=l"(d) : "l"(a), "l"(b));
}
__device__ __forceinline__ unsigned long long xadd16(unsigned long long v) {
    unsigned lo = (unsigned)v, hi = (unsigned)(v >> 32);
    unsigned olo = __shfl_xor_sync(0xffffffffu, lo, 16);
    unsigned ohi = __shfl_xor_sync(0xffffffffu, hi, 16);
    unsigned long long o = pk2u(olo, ohi);
    add2(v, v, o);
    return v;
}
__device__ __forceinline__ float lrelu(float x) { return fmaxf(x, 0.01f * x); }

// ---------------- k1: one-pass build: bucket scatter + rel weights ----------------
// g_cnt / g_w are zero on entry (zero-init statics; fused consumes-and-zeroes).
__global__ void build_kernel(const int* __restrict__ row1, const int* __restrict__ col1,
                             const float* __restrict__ val1,
                             const int* __restrict__ row2, const int* __restrict__ relix,
                             const float* __restrict__ valr, int e) {
    int i = blockIdx.x * blockDim.x + threadIdx.x;
    int e4 = e >> 2;
    if (i < e4) {
        int4 r1 = ((const int4*)row1)[i];
        int4 c1 = ((const int4*)col1)[i];
        float4 v1 = ((const float4*)val1)[i];
        int4 r2 = ((const int4*)row2)[i];
        int4 rl = ((const int4*)relix)[i];
        float4 vr = ((const float4*)valr)[i];
        int p0 = atomicAdd(&g_cnt[r1.x], 1);
        int p1 = atomicAdd(&g_cnt[r1.y], 1);
        int p2 = atomicAdd(&g_cnt[r1.z], 1);
        int p3 = atomicAdd(&g_cnt[r1.w], 1);
        if (p0 < CAP) g_es[(size_t)r1.x * CAP + p0] =
            (unsigned long long)(unsigned)c1.x | ((unsigned long long)__float_as_uint(v1.x) << 32);
        if (p1 < CAP) g_es[(size_t)r1.y * CAP + p1] =
            (unsigned long long)(unsigned)c1.y | ((unsigned long long)__float_as_uint(v1.y) << 32);
        if (p2 < CAP) g_es[(size_t)r1.z * CAP + p2] =
            (unsigned long long)(unsigned)c1.z | ((unsigned long long)__float_as_uint(v1.z) << 32);
        if (p3 < CAP) g_es[(size_t)r1.w * CAP + p3] =
            (unsigned long long)(unsigned)c1.w | ((unsigned long long)__float_as_uint(v1.w) << 32);
        atomicAdd(&g_w[r2.x * NREL + rl.x], vr.x);
        atomicAdd(&g_w[r2.y * NREL + rl.y], vr.y);
        atomicAdd(&g_w[r2.z * NREL + rl.z], vr.z);
        atomicAdd(&g_w[r2.w * NREL + rl.w], vr.w);
    }
    if (i < (e & 3)) {
        int idx = (e & ~3) + i;
        int r = row1[idx];
        int p = atomicAdd(&g_cnt[r], 1);
        if (p < CAP) g_es[(size_t)r * CAP + p] =
            (unsigned long long)(unsigned)col1[idx] |
            ((unsigned long long)__float_as_uint(val1[idx]) << 32);
        atomicAdd(&g_w[row2[idx] * NREL + relix[idx]], valr[idx]);
    }
}

// ---------------- k2: fused gather + batched rel + batched matvecs ----------------
// Half-warp specialization: lanes 0-15 = half 0, lanes 16-31 = half 1.
// Lane owns dims qd..qd+3. 8 rows per warp batch:
//   phase 1  : per-row edge gather (predicated 16-edge batches) -> sGat (=sAdd)
//   phase 1.5: rel matvec for all 8 rows in ONE sRel pass (w in regs, shfl bcast)
//   phase 2  : two 64x64 matvecs for 8 rows (sW read amortized 8x)
__global__ __launch_bounds__(256) void fused_kernel(
    const float* __restrict__ ego, const float* __restrict__ rel,
    const float* __restrict__ W1, const float* __restrict__ b1,
    const float* __restrict__ W2, const float* __restrict__ b2,
    float* __restrict__ out, int n) {
    extern __shared__ __align__(16) float sm[];
    float* sW1  = sm;            // [k][d] = W1[d][k]     4096
    float* sW2  = sm + 4096;     // [k][d] = W2[d][k]     4096
    float* sRel = sm + 8192;     // [rel][d]              2048
    float* sAdd = sm + 10240;    // 8 warps x 8 rows x 64 4096
    float* sProd= sm + 14336;    // same                  4096
    // total 18432 floats = 73728 B -> 3 blocks/SM

    int tid = threadIdx.x, lane = tid & 31, w = tid >> 5;
    int half = lane >> 4;
    int qd = (lane & 15) * 4;

    for (int i = tid; i < NDIM * NDIM; i += 256) {
        int k = i >> 6, d = i & 63;
        sW1[i] = W1[d * NDIM + k];
        sW2[i] = W2[d * NDIM + k];
    }
    for (int i = tid; i < NREL * NDIM; i += 256) sRel[i] = rel[i];
    __syncthreads();

    const float* bsrc = half ? b2 : b1;
    float4 bv4 = *(const float4*)(bsrc + qd);
    unsigned long long bb0 = pk2f(bv4.x, bv4.y), bb1 = pk2f(bv4.z, bv4.w);
    const unsigned long long c01 = pk2f(0.1f, 0.1f);

    float* myAdd = sAdd + w * (RPW * NDIM);
    float* myProd = sProd + w * (RPW * NDIM);
    const float* sW = half ? sW2 : sW1;
    const float* sap = (half ? sProd : sAdd) + w * (RPW * NDIM);

    int slot = blockIdx.x * 8 + w;
    int nslots = gridDim.x * 8;
    int t0 = half * 16;

    for (int base = slot * RPW; base < n; base += nslots * RPW) {
        float wv_l[RPW];
        // ================= phase 1: per-row edge gather =================
#pragma unroll
        for (int j = 0; j < RPW; ++j) {
            int r = base + j;
            if (r >= n) { wv_l[j] = 0.0f; continue; }
            unsigned long long aA = 0, aB = 0;
            int ebase = r * CAP;
            int cnt = g_cnt[r];
            if (cnt > CAP) cnt = CAP;
            __syncwarp();
            if (lane == 0) g_cnt[r] = 0;          // consume-and-zero
            int iters = (cnt + 15) >> 4;
            for (int it = 0; it < iters; ++it) {
                int e = ebase + it * 16;
                int rem = cnt - it * 16;
                unsigned long long ds[8];
#pragma unroll
                for (int i = 0; i < 8; ++i) ds[i] = g_es[e + 2 * i + half];
                ulonglong2 xs[8];
#pragma unroll
                for (int i = 0; i < 8; ++i) {
                    unsigned c = (unsigned)ds[i];   // OOB slots: 0 or stale valid col
                    xs[i] = *(const ulonglong2*)(ego + (size_t)c * NDIM + qd);
                }
#pragma unroll
                for (int i = 0; i < 8; ++i) {
                    float v = (2 * i + half) < rem
                            ? __uint_as_float((unsigned)(ds[i] >> 32)) : 0.0f;
                    unsigned long long vv = pk2f(v, v);
                    fma2(aA, vv, xs[i].x, aA);
                    fma2(aB, vv, xs[i].y, aB);
                }
            }
            aA = xadd16(aA);
            aB = xadd16(aB);
            if (half == 0) {
                ulonglong2 st; st.x = aA; st.y = aB;
                *(ulonglong2*)&myAdd[j * NDIM + qd] = st;   // gather partial
            }
            wv_l[j] = g_w[r * NREL + lane];
            g_w[r * NREL + lane] = 0.0f;          // consume-and-zero
        }
        __syncwarp();

        // ============ phase 1.5: batched rel matvec (one sRel pass / 8 rows) ============
        unsigned long long relA[RPW], relB[RPW];
#pragma unroll
        for (int j = 0; j < RPW; ++j) { relA[j] = 0; relB[j] = 0; }
#pragma unroll 4
        for (int t = 0; t < 16; ++t) {
            ulonglong2 rv = *(const ulonglong2*)&sRel[(t0 + t) * NDIM + qd];
#pragma unroll
            for (int j = 0; j < RPW; ++j) {
                float wv = __shfl_sync(0xffffffffu, wv_l[j], t0 + t);
                unsigned long long vv = pk2f(wv, wv);
                fma2(relA[j], vv, rv.x, relA[j]);
                fma2(relB[j], vv, rv.y, relB[j]);
            }
        }
#pragma unroll
        for (int j = 0; j < RPW; ++j) {
            int r = base + j;
            if (r >= n) break;
            unsigned long long rA = xadd16(relA[j]);
            unsigned long long rB = xadd16(relB[j]);
            ulonglong2 gt = *(const ulonglong2*)&myAdd[j * NDIM + qd];
            unsigned long long sideA, sideB;
            fma2(sideA, c01, rA, gt.x);
            fma2(sideB, c01, rB, gt.y);
            ulonglong2 eg = *(const ulonglong2*)(ego + (size_t)r * NDIM + qd);
            unsigned long long adA, adB, pA, pB;
            add2(adA, eg.x, sideA); add2(adB, eg.y, sideB);
            mul2(pA, eg.x, sideA);  mul2(pB, eg.y, sideB);
            if (half == 0) {
                ulonglong2 st;
                st.x = adA; st.y = adB;
                *(ulonglong2*)&myAdd[j * NDIM + qd] = st;
                st.x = pA; st.y = pB;
                *(ulonglong2*)&myProd[j * NDIM + qd] = st;
            }
        }
        __syncwarp();

        // ================= phase 2: two 64x64 matvecs, 8 rows =================
        unsigned long long acc[RPW][2];
#pragma unroll
        for (int j = 0; j < RPW; ++j) { acc[j][0] = 0; acc[j][1] = 0; }
#pragma unroll 4
        for (int k = 0; k < NDIM; ++k) {
            ulonglong2 wv = *(const ulonglong2*)&sW[k * NDIM + qd];
#pragma unroll
            for (int j = 0; j < RPW; ++j) {
                float a = sap[j * NDIM + k];
                unsigned long long aa = pk2f(a, a);
                fma2(acc[j][0], aa, wv.x, acc[j][0]);
                fma2(acc[j][1], aa, wv.y, acc[j][1]);
            }
        }
#pragma unroll
        for (int j = 0; j < RPW; ++j) {
            int r = base + j;
            if (r >= n) break;
            unsigned long long m0, m1;
            add2(m0, acc[j][0], bb0);
            add2(m1, acc[j][1], bb1);
            float f0, f1, f2, f3;
            up2(f0, f1, m0);
            up2(f2, f3, m1);
            f0 = lrelu(f0); f1 = lrelu(f1); f2 = lrelu(f2); f3 = lrelu(f3);
            f0 += __shfl_xor_sync(0xffffffffu, f0, 16);
            f1 += __shfl_xor_sync(0xffffffffu, f1, 16);
            f2 += __shfl_xor_sync(0xffffffffu, f2, 16);
            f3 += __shfl_xor_sync(0xffffffffu, f3, 16);
            if (half == 0) {
                float4 ov = { f0, f1, f2, f3 };
                *(float4*)(out + (size_t)r * NDIM + qd) = ov;
            }
        }
        __syncwarp();
    }
}

// ---------------- launch ----------------
extern "C" void kernel_launch(void* const* d_in, const int* in_sizes, int n_in,
                              void* d_out, int out_size) {
    const float* ego   = (const float*)d_in[0];
    const float* rel   = (const float*)d_in[1];
    const int*   row1  = (const int*)d_in[2];
    const int*   col1  = (const int*)d_in[3];
    const float* vals1 = (const float*)d_in[4];
    const int*   row2  = (const int*)d_in[5];
    const int*   relix = (const int*)d_in[6];
    const float* vals2 = (const float*)d_in[7];
    const float* W1    = (const float*)d_in[8];
    const float* b1    = (const float*)d_in[9];
    const float* W2    = (const float*)d_in[10];
    const float* b2    = (const float*)d_in[11];
    float* out = (float*)d_out;

    int n = in_sizes[0] / NDIM;   // 100000
    int e = in_sizes[2];          // 3200000

    build_kernel<<<(e / 4 + 255) / 256, 256>>>(row1, col1, vals1, row2, relix, vals2, e);

    size_t smemBytes = (size_t)(4096 + 4096 + 2048 + 4096 + 4096) * sizeof(float); // 73728 B
    cudaFuncSetAttribute(fused_kernel, cudaFuncAttributeMaxDynamicSharedMemorySize,
                         (int)smemBytes);
    int smCount = 148;
    cudaDeviceGetAttribute(&smCount, cudaDevAttrMultiProcessorCount, 0);
    int blocksPerSM = 2;
    cudaOccupancyMaxActiveBlocksPerMultiprocessor(&blocksPerSM, fused_kernel, 256,
                                                  smemBytes);
    if (blocksPerSM < 1) blocksPerSM = 1;
    int grid = smCount * blocksPerSM;
    fused_kernel<<<grid, 256, smemBytes>>>(ego, rel, W1, b1, W2, b2, out, n);
}

// round 11
// speedup vs baseline: 1.0403x; 1.0403x over previous
#include <cuda_runtime.h>
#include <cuda_bf16.h>

#define NDIM 64
#define MAXN 100000
#define MAXE 3200000
#define NREL 32
#define CAP 128          // padded bucket capacity per row (degree ~Poisson(32))
#define RPW 4            // rows per warp batch (8 spilled — see R10)

// ---------------- device scratch (no allocations allowed; zero-initialized) ----------------
__device__ int g_cnt[MAXN];
__device__ float g_w[MAXN * NREL];                       // per-(node, rel) weights
__device__ unsigned long long g_es[(size_t)MAXN * CAP];  // padded buckets: (col, val)

// ---------------- packed f32x2 helpers (sm_103a) ----------------
__device__ __forceinline__ unsigned long long pk2f(float lo, float hi) {
    unsigned long long r;
    asm("mov.b64 %0, {%1, %2};" : "=l"(r) : "r"(__float_as_uint(lo)), "r"(__float_as_uint(hi)));
    return r;
}
__device__ __forceinline__ unsigned long long pk2u(unsigned lo, unsigned hi) {
    unsigned long long r;
    asm("mov.b64 %0, {%1, %2};" : "=l"(r) : "r"(lo), "r"(hi));
    return r;
}
__device__ __forceinline__ void up2(float& lo, float& hi, unsigned long long v) {
    unsigned a, b;
    asm("mov.b64 {%0, %1}, %2;" : "=r"(a), "=r"(b) : "l"(v));
    lo = __uint_as_float(a); hi = __uint_as_float(b);
}
__device__ __forceinline__ void fma2(unsigned long long& d, unsigned long long a,
                                     unsigned long long b, unsigned long long c) {
    asm("fma.rn.f32x2 %0, %1, %2, %3;" : "=l"(d) : "l"(a), "l"(b), "l"(c));
}
__device__ __forceinline__ void add2(unsigned long long& d, unsigned long long a,
                                     unsigned long long b) {
    asm("add.rn.f32x2 %0, %1, %2;" : "=l"(d) : "l"(a), "l"(b));
}
__device__ __forceinline__ void mul2(unsigned long long& d, unsigned long long a,
                                     unsigned long long b) {
    asm("mul.rn.f32x2 %0, %1, %2;" : "=l"(d) : "l"(a), "l"(b));
}
__device__ __forceinline__ unsigned long long xadd16(unsigned long long v) {
    unsigned lo = (unsigned)v, hi = (unsigned)(v >> 32);
    unsigned olo = __shfl_xor_sync(0xffffffffu, lo, 16);
    unsigned ohi = __shfl_xor_sync(0xffffffffu, hi, 16);
    unsigned long long o = pk2u(olo, ohi);
    add2(v, v, o);
    return v;
}
__device__ __forceinline__ float lrelu(float x) { return fmaxf(x, 0.01f * x); }

// ---------------- k1: one-pass build: bucket scatter + rel weights ----------------
// g_cnt / g_w are zero on entry (zero-init statics; fused consumes-and-zeroes).
__global__ void build_kernel(const int* __restrict__ row1, const int* __restrict__ col1,
                             const float* __restrict__ val1,
                             const int* __restrict__ row2, const int* __restrict__ relix,
                             const float* __restrict__ valr, int e) {
    int i = blockIdx.x * blockDim.x + threadIdx.x;
    int e4 = e >> 2;
    if (i < e4) {
        int4 r1 = ((const int4*)row1)[i];
        int4 c1 = ((const int4*)col1)[i];
        float4 v1 = ((const float4*)val1)[i];
        int4 r2 = ((const int4*)row2)[i];
        int4 rl = ((const int4*)relix)[i];
        float4 vr = ((const float4*)valr)[i];
        int p0 = atomicAdd(&g_cnt[r1.x], 1);
        int p1 = atomicAdd(&g_cnt[r1.y], 1);
        int p2 = atomicAdd(&g_cnt[r1.z], 1);
        int p3 = atomicAdd(&g_cnt[r1.w], 1);
        if (p0 < CAP) g_es[(size_t)r1.x * CAP + p0] =
            (unsigned long long)(unsigned)c1.x | ((unsigned long long)__float_as_uint(v1.x) << 32);
        if (p1 < CAP) g_es[(size_t)r1.y * CAP + p1] =
            (unsigned long long)(unsigned)c1.y | ((unsigned long long)__float_as_uint(v1.y) << 32);
        if (p2 < CAP) g_es[(size_t)r1.z * CAP + p2] =
            (unsigned long long)(unsigned)c1.z | ((unsigned long long)__float_as_uint(v1.z) << 32);
        if (p3 < CAP) g_es[(size_t)r1.w * CAP + p3] =
            (unsigned long long)(unsigned)c1.w | ((unsigned long long)__float_as_uint(v1.w) << 32);
        atomicAdd(&g_w[r2.x * NREL + rl.x], vr.x);
        atomicAdd(&g_w[r2.y * NREL + rl.y], vr.y);
        atomicAdd(&g_w[r2.z * NREL + rl.z], vr.z);
        atomicAdd(&g_w[r2.w * NREL + rl.w], vr.w);
    }
    if (i < (e & 3)) {
        int idx = (e & ~3) + i;
        int r = row1[idx];
        int p = atomicAdd(&g_cnt[r], 1);
        if (p < CAP) g_es[(size_t)r * CAP + p] =
            (unsigned long long)(unsigned)col1[idx] |
            ((unsigned long long)__float_as_uint(val1[idx]) << 32);
        atomicAdd(&g_w[row2[idx] * NREL + relix[idx]], valr[idx]);
    }
}

// ---------------- k2: fused gather + batched rel + batched matvecs ----------------
// Half-warp specialization: lanes 0-15 = half 0, lanes 16-31 = half 1.
// Lane owns dims qd..qd+3. 4 rows per warp batch:
//   phase 1  : per-row edge gather (predicated 16-edge batches) -> sAdd partials
//   phase 1.5: rel matvec for all 4 rows in ONE sRel pass (w in regs, shfl bcast)
//   phase 2  : two 64x64 matvecs for 4 rows (sW read amortized 4x)
__global__ __launch_bounds__(256) void fused_kernel(
    const float* __restrict__ ego, const float* __restrict__ rel,
    const float* __restrict__ W1, const float* __restrict__ b1,
    const float* __restrict__ W2, const float* __restrict__ b2,
    float* __restrict__ out, int n) {
    extern __shared__ __align__(16) float sm[];
    float* sW1  = sm;            // [k][d] = W1[d][k]     4096
    float* sW2  = sm + 4096;     // [k][d] = W2[d][k]     4096
    float* sRel = sm + 8192;     // [rel][d]              2048
    float* sAdd = sm + 10240;    // 8 warps x 4 rows x 64 2048
    float* sProd= sm + 12288;    // same                  2048
    // total 14336 floats = 57344 B

    int tid = threadIdx.x, lane = tid & 31, w = tid >> 5;
    int half = lane >> 4;
    int qd = (lane & 15) * 4;

    for (int i = tid; i < NDIM * NDIM; i += 256) {
        int k = i >> 6, d = i & 63;
        sW1[i] = W1[d * NDIM + k];
        sW2[i] = W2[d * NDIM + k];
    }
    for (int i = tid; i < NREL * NDIM; i += 256) sRel[i] = rel[i];
    __syncthreads();

    const float* bsrc = half ? b2 : b1;
    float4 bv4 = *(const float4*)(bsrc + qd);
    unsigned long long bb0 = pk2f(bv4.x, bv4.y), bb1 = pk2f(bv4.z, bv4.w);
    const unsigned long long c01 = pk2f(0.1f, 0.1f);

    float* myAdd = sAdd + w * (RPW * NDIM);
    float* myProd = sProd + w * (RPW * NDIM);
    const float* sW = half ? sW2 : sW1;
    const float* sap = (half ? sProd : sAdd) + w * (RPW * NDIM);

    int slot = blockIdx.x * 8 + w;
    int nslots = gridDim.x * 8;
    int t0 = half * 16;

    for (int base = slot * RPW; base < n; base += nslots * RPW) {
        float wv_l[RPW];
        // ================= phase 1: per-row edge gather =================
#pragma unroll
        for (int j = 0; j < RPW; ++j) {
            int r = base + j;
            if (r >= n) { wv_l[j] = 0.0f; continue; }
            unsigned long long aA = 0, aB = 0;
            int ebase = r * CAP;
            int cnt = g_cnt[r];
            if (cnt > CAP) cnt = CAP;
            __syncwarp();
            if (lane == 0) g_cnt[r] = 0;          // consume-and-zero
            int iters = (cnt + 15) >> 4;
            for (int it = 0; it < iters; ++it) {
                int e = ebase + it * 16;
                int rem = cnt - it * 16;
                unsigned long long ds[8];
#pragma unroll
                for (int i = 0; i < 8; ++i) ds[i] = g_es[e + 2 * i + half];
                ulonglong2 xs[8];
#pragma unroll
                for (int i = 0; i < 8; ++i) {
                    unsigned c = (unsigned)ds[i];   // OOB slots: 0 or stale valid col
                    xs[i] = *(const ulonglong2*)(ego + (size_t)c * NDIM + qd);
                }
#pragma unroll
                for (int i = 0; i < 8; ++i) {
                    float v = (2 * i + half) < rem
                            ? __uint_as_float((unsigned)(ds[i] >> 32)) : 0.0f;
                    unsigned long long vv = pk2f(v, v);
                    fma2(aA, vv, xs[i].x, aA);
                    fma2(aB, vv, xs[i].y, aB);
                }
            }
            aA = xadd16(aA);
            aB = xadd16(aB);
            if (half == 0) {
                ulonglong2 st; st.x = aA; st.y = aB;
                *(ulonglong2*)&myAdd[j * NDIM + qd] = st;   // gather partial
            }
            wv_l[j] = g_w[r * NREL + lane];
            g_w[r * NREL + lane] = 0.0f;          // consume-and-zero
        }
        __syncwarp();

        // ============ phase 1.5: batched rel matvec (one sRel pass / 4 rows) ============
        unsigned long long relA[RPW], relB[RPW];
#pragma unroll
        for (int j = 0; j < RPW; ++j) { relA[j] = 0; relB[j] = 0; }
#pragma unroll 4
        for (int t = 0; t < 16; ++t) {
            ulonglong2 rv = *(const ulonglong2*)&sRel[(t0 + t) * NDIM + qd];
#pragma unroll
            for (int j = 0; j < RPW; ++j) {
                float wv = __shfl_sync(0xffffffffu, wv_l[j], t0 + t);
                unsigned long long vv = pk2f(wv, wv);
                fma2(relA[j], vv, rv.x, relA[j]);
                fma2(relB[j], vv, rv.y, relB[j]);
            }
        }
#pragma unroll
        for (int j = 0; j < RPW; ++j) {
            int r = base + j;
            if (r >= n) break;
            unsigned long long rA = xadd16(relA[j]);
            unsigned long long rB = xadd16(relB[j]);
            ulonglong2 gt = *(const ulonglong2*)&myAdd[j * NDIM + qd];
            unsigned long long sideA, sideB;
            fma2(sideA, c01, rA, gt.x);
            fma2(sideB, c01, rB, gt.y);
            ulonglong2 eg = *(const ulonglong2*)(ego + (size_t)r * NDIM + qd);
            unsigned long long adA, adB, pA, pB;
            add2(adA, eg.x, sideA); add2(adB, eg.y, sideB);
            mul2(pA, eg.x, sideA);  mul2(pB, eg.y, sideB);
            if (half == 0) {
                ulonglong2 st;
                st.x = adA; st.y = adB;
                *(ulonglong2*)&myAdd[j * NDIM + qd] = st;
                st.x = pA; st.y = pB;
                *(ulonglong2*)&myProd[j * NDIM + qd] = st;
            }
        }
        __syncwarp();

        // ================= phase 2: two 64x64 matvecs, 4 rows =================
        unsigned long long acc[RPW][2];
#pragma unroll
        for (int j = 0; j < RPW; ++j) { acc[j][0] = 0; acc[j][1] = 0; }
#pragma unroll 4
        for (int k = 0; k < NDIM; ++k) {
            ulonglong2 wv = *(const ulonglong2*)&sW[k * NDIM + qd];
#pragma unroll
            for (int j = 0; j < RPW; ++j) {
                float a = sap[j * NDIM + k];
                unsigned long long aa = pk2f(a, a);
                fma2(acc[j][0], aa, wv.x, acc[j][0]);
                fma2(acc[j][1], aa, wv.y, acc[j][1]);
            }
        }
#pragma unroll
        for (int j = 0; j < RPW; ++j) {
            int r = base + j;
            if (r >= n) break;
            unsigned long long m0, m1;
            add2(m0, acc[j][0], bb0);
            add2(m1, acc[j][1], bb1);
            float f0, f1, f2, f3;
            up2(f0, f1, m0);
            up2(f2, f3, m1);
            f0 = lrelu(f0); f1 = lrelu(f1); f2 = lrelu(f2); f3 = lrelu(f3);
            f0 += __shfl_xor_sync(0xffffffffu, f0, 16);
            f1 += __shfl_xor_sync(0xffffffffu, f1, 16);
            f2 += __shfl_xor_sync(0xffffffffu, f2, 16);
            f3 += __shfl_xor_sync(0xffffffffu, f3, 16);
            if (half == 0) {
                float4 ov = { f0, f1, f2, f3 };
                *(float4*)(out + (size_t)r * NDIM + qd) = ov;
            }
        }
        __syncwarp();
    }
}

// ---------------- launch ----------------
extern "C" void kernel_launch(void* const* d_in, const int* in_sizes, int n_in,
                              void* d_out, int out_size) {
    const float* ego   = (const float*)d_in[0];
    const float* rel   = (const float*)d_in[1];
    const int*   row1  = (const int*)d_in[2];
    const int*   col1  = (const int*)d_in[3];
    const float* vals1 = (const float*)d_in[4];
    const int*   row2  = (const int*)d_in[5];
    const int*   relix = (const int*)d_in[6];
    const float* vals2 = (const float*)d_in[7];
    const float* W1    = (const float*)d_in[8];
    const float* b1    = (const float*)d_in[9];
    const float* W2    = (const float*)d_in[10];
    const float* b2    = (const float*)d_in[11];
    float* out = (float*)d_out;

    int n = in_sizes[0] / NDIM;   // 100000
    int e = in_sizes[2];          // 3200000

    build_kernel<<<(e / 4 + 255) / 256, 256>>>(row1, col1, vals1, row2, relix, vals2, e);

    size_t smemBytes = (size_t)(4096 + 4096 + 2048 + 2048 + 2048) * sizeof(float); // 57344 B
    cudaFuncSetAttribute(fused_kernel, cudaFuncAttributeMaxDynamicSharedMemorySize,
                         (int)smemBytes);
    int smCount = 148;
    cudaDeviceGetAttribute(&smCount, cudaDevAttrMultiProcessorCount, 0);
    int blocksPerSM = 2;
    cudaOccupancyMaxActiveBlocksPerMultiprocessor(&blocksPerSM, fused_kernel, 256,
                                                  smemBytes);
    if (blocksPerSM < 1) blocksPerSM = 1;
    int grid = smCount * blocksPerSM;
    fused_kernel<<<grid, 256, smemBytes>>>(ego, rel, W1, b1, W2, b2, out, n);
}

// round 12
// speedup vs baseline: 1.3844x; 1.3307x over previous
#include <cuda_runtime.h>
#include <cuda_bf16.h>

#define NDIM 64
#define MAXN 100000
#define MAXE 3200000
#define NREL 32
#define CAP 128          // padded bucket capacity per row (degree ~Poisson(32))

// ---------------- device scratch (no allocations allowed; zero-initialized) ----------------
__device__ int g_cnt[MAXN];
__device__ float g_w[MAXN * NREL];                       // per-(node, rel) weights
__device__ unsigned long long g_es[(size_t)MAXN * CAP];  // padded buckets: (col, val)

// ---------------- packed f32x2 helpers (sm_103a) ----------------
__device__ __forceinline__ unsigned long long pk2f(float lo, float hi) {
    unsigned long long r;
    asm("mov.b64 %0, {%1, %2};" : "=l"(r) : "r"(__float_as_uint(lo)), "r"(__float_as_uint(hi)));
    return r;
}
__device__ __forceinline__ unsigned long long pk2u(unsigned lo, unsigned hi) {
    unsigned long long r;
    asm("mov.b64 %0, {%1, %2};" : "=l"(r) : "r"(lo), "r"(hi));
    return r;
}
__device__ __forceinline__ void up2(float& lo, float& hi, unsigned long long v) {
    unsigned a, b;
    asm("mov.b64 {%0, %1}, %2;" : "=r"(a), "=r"(b) : "l"(v));
    lo = __uint_as_float(a); hi = __uint_as_float(b);
}
__device__ __forceinline__ void fma2(unsigned long long& d, unsigned long long a,
                                     unsigned long long b, unsigned long long c) {
    asm("fma.rn.f32x2 %0, %1, %2, %3;" : "=l"(d) : "l"(a), "l"(b), "l"(c));
}
__device__ __forceinline__ void add2(unsigned long long& d, unsigned long long a,
                                     unsigned long long b) {
    asm("add.rn.f32x2 %0, %1, %2;" : "=l"(d) : "l"(a), "l"(b));
}
__device__ __forceinline__ void mul2(unsigned long long& d, unsigned long long a,
                                     unsigned long long b) {
    asm("mul.rn.f32x2 %0, %1, %2;" : "=l"(d) : "l"(a), "l"(b));
}
__device__ __forceinline__ unsigned long long xadd16(unsigned long long v) {
    unsigned lo = (unsigned)v, hi = (unsigned)(v >> 32);
    unsigned olo = __shfl_xor_sync(0xffffffffu, lo, 16);
    unsigned ohi = __shfl_xor_sync(0xffffffffu, hi, 16);
    unsigned long long o = pk2u(olo, ohi);
    add2(v, v, o);
    return v;
}
__device__ __forceinline__ float lrelu(float x) { return fmaxf(x, 0.01f * x); }

// ---------------- k1: one-pass build: bucket scatter + rel weights ----------------
// g_cnt / g_w are zero on entry (zero-init statics; fused consumes-and-zeroes).
__global__ void build_kernel(const int* __restrict__ row1, const int* __restrict__ col1,
                             const float* __restrict__ val1,
                             const int* __restrict__ row2, const int* __restrict__ relix,
                             const float* __restrict__ valr, int e) {
    int i = blockIdx.x * blockDim.x + threadIdx.x;
    int e4 = e >> 2;
    if (i < e4) {
        int4 r1 = ((const int4*)row1)[i];
        int4 c1 = ((const int4*)col1)[i];
        float4 v1 = ((const float4*)val1)[i];
        int4 r2 = ((const int4*)row2)[i];
        int4 rl = ((const int4*)relix)[i];
        float4 vr = ((const float4*)valr)[i];
        int p0 = atomicAdd(&g_cnt[r1.x], 1);
        int p1 = atomicAdd(&g_cnt[r1.y], 1);
        int p2 = atomicAdd(&g_cnt[r1.z], 1);
        int p3 = atomicAdd(&g_cnt[r1.w], 1);
        if (p0 < CAP) g_es[(size_t)r1.x * CAP + p0] =
            (unsigned long long)(unsigned)c1.x | ((unsigned long long)__float_as_uint(v1.x) << 32);
        if (p1 < CAP) g_es[(size_t)r1.y * CAP + p1] =
            (unsigned long long)(unsigned)c1.y | ((unsigned long long)__float_as_uint(v1.y) << 32);
        if (p2 < CAP) g_es[(size_t)r1.z * CAP + p2] =
            (unsigned long long)(unsigned)c1.z | ((unsigned long long)__float_as_uint(v1.z) << 32);
        if (p3 < CAP) g_es[(size_t)r1.w * CAP + p3] =
            (unsigned long long)(unsigned)c1.w | ((unsigned long long)__float_as_uint(v1.w) << 32);
        atomicAdd(&g_w[r2.x * NREL + rl.x], vr.x);
        atomicAdd(&g_w[r2.y * NREL + rl.y], vr.y);
        atomicAdd(&g_w[r2.z * NREL + rl.z], vr.z);
        atomicAdd(&g_w[r2.w * NREL + rl.w], vr.w);
    }
    if (i < (e & 3)) {
        int idx = (e & ~3) + i;
        int r = row1[idx];
        int p = atomicAdd(&g_cnt[r], 1);
        if (p < CAP) g_es[(size_t)r * CAP + p] =
            (unsigned long long)(unsigned)col1[idx] |
            ((unsigned long long)__float_as_uint(val1[idx]) << 32);
        atomicAdd(&g_w[row2[idx] * NREL + relix[idx]], valr[idx]);
    }
}

// ---------------- k2: fused gather-SPMM + rel-dense + 2 matvecs (R9 shell) ----------------
// Half-warp specialization: lanes 0-15 = half 0, lanes 16-31 = half 1.
// Each lane owns 4 dims (qd..qd+3). Gather: uniform predicated 16-edge batches.
// Rel matvec inline per row (R9 structure). Matvec phase 2: k-loop blocked by 4
// with float4 a-broadcasts (4x fewer LDS broadcast instructions).
// Consumes-and-zeroes g_cnt / g_w for the next launch.
__global__ __launch_bounds__(256) void fused_kernel(
    const float* __restrict__ ego, const float* __restrict__ rel,
    const float* __restrict__ W1, const float* __restrict__ b1,
    const float* __restrict__ W2, const float* __restrict__ b2,
    float* __restrict__ out, int n) {
    extern __shared__ __align__(16) float sm[];
    float* sW1  = sm;            // [k][d] = W1[d][k]     4096 floats
    float* sW2  = sm + 4096;     // [k][d] = W2[d][k]     4096 floats
    float* sRel = sm + 8192;     // [rel][d]              2048 floats
    float* sAdd = sm + 10240;    // 8 warps x 4 rows x 64 2048 floats
    float* sProd= sm + 12288;    // same                  2048 floats

    int tid = threadIdx.x, lane = tid & 31, w = tid >> 5;
    int half = lane >> 4;
    int qd = (lane & 15) * 4;

    for (int i = tid; i < NDIM * NDIM; i += 256) {
        int k = i >> 6, d = i & 63;
        sW1[i] = W1[d * NDIM + k];
        sW2[i] = W2[d * NDIM + k];
    }
    for (int i = tid; i < NREL * NDIM; i += 256) sRel[i] = rel[i];
    __syncthreads();

    const float* bsrc = half ? b2 : b1;
    float4 bv4 = *(const float4*)(bsrc + qd);
    unsigned long long bb0 = pk2f(bv4.x, bv4.y), bb1 = pk2f(bv4.z, bv4.w);
    const unsigned long long c01 = pk2f(0.1f, 0.1f);

    float* myAdd = sAdd + w * 256;
    float* myProd = sProd + w * 256;
    const float* sW = half ? sW2 : sW1;
    const float* sap = (half ? sProd : sAdd) + w * 256;

    int slot = blockIdx.x * 8 + w;
    int nslots = gridDim.x * 8;

    for (int base = slot * 4; base < n; base += nslots * 4) {
        // ================= phase 1: gather + inline rel + side (R9) =================
#pragma unroll
        for (int j = 0; j < 4; ++j) {
            int r = base + j;
            if (r >= n) break;
            unsigned long long aA = 0, aB = 0;
            int ebase = r * CAP;
            int cnt = g_cnt[r];
            if (cnt > CAP) cnt = CAP;
            __syncwarp();
            if (lane == 0) g_cnt[r] = 0;          // consume-and-zero for next launch
            int iters = (cnt + 15) >> 4;
            for (int it = 0; it < iters; ++it) {
                int e = ebase + it * 16;
                int rem = cnt - it * 16;          // 1..16 valid edges in this batch
                unsigned long long ds[8];
#pragma unroll
                for (int i = 0; i < 8; ++i) ds[i] = g_es[e + 2 * i + half];
                ulonglong2 xs[8];
#pragma unroll
                for (int i = 0; i < 8; ++i) {
                    // OOB slots: 0 or stale-but-valid col -> always a safe index
                    unsigned c = (unsigned)ds[i];
                    xs[i] = *(const ulonglong2*)(ego + (size_t)c * NDIM + qd);
                }
#pragma unroll
                for (int i = 0; i < 8; ++i) {
                    float v = (2 * i + half) < rem
                            ? __uint_as_float((unsigned)(ds[i] >> 32)) : 0.0f;
                    unsigned long long vv = pk2f(v, v);
                    fma2(aA, vv, xs[i].x, aA);
                    fma2(aB, vv, xs[i].y, aB);
                }
            }
            // rel side: this half handles 16 of 32 relations
            unsigned long long rA = 0, rB = 0;
            float wv_l = g_w[r * NREL + lane];
            g_w[r * NREL + lane] = 0.0f;          // consume-and-zero for next launch
            int t0 = half * 16;
#pragma unroll
            for (int t = 0; t < 16; ++t) {
                float wv = __shfl_sync(0xffffffffu, wv_l, t0 + t);
                if (wv != 0.0f) {
                    ulonglong2 rv = *(const ulonglong2*)&sRel[(t0 + t) * NDIM + qd];
                    unsigned long long vv = pk2f(wv, wv);
                    fma2(rA, vv, rv.x, rA);
                    fma2(rB, vv, rv.y, rB);
                }
            }
            fma2(aA, c01, rA, aA);
            fma2(aB, c01, rB, aB);
            // combine halves -> full side in all lanes
            aA = xadd16(aA);
            aB = xadd16(aB);
            ulonglong2 eg = *(const ulonglong2*)(ego + (size_t)r * NDIM + qd);
            unsigned long long adA, adB, pA, pB;
            add2(adA, eg.x, aA); add2(adB, eg.y, aB);
            mul2(pA, eg.x, aA);  mul2(pB, eg.y, aB);
            if (half == 0) {
                ulonglong2 st;
                st.x = adA; st.y = adB;
                *(ulonglong2*)&myAdd[j * NDIM + qd] = st;
                st.x = pA; st.y = pB;
                *(ulonglong2*)&myProd[j * NDIM + qd] = st;
            }
        }
        __syncwarp();

        // ============ phase 2: two 64x64 matvecs, k blocked by 4 (float4 a-loads) ============
        unsigned long long acc[4][2];
#pragma unroll
        for (int j = 0; j < 4; ++j) { acc[j][0] = 0; acc[j][1] = 0; }
#pragma unroll 2
        for (int k4 = 0; k4 < NDIM; k4 += 4) {
            // one LDS.128 broadcast per row covers 4 k-values (was 4 scalar LDS)
            float4 av0 = *(const float4*)&sap[0 * NDIM + k4];
            float4 av1 = *(const float4*)&sap[1 * NDIM + k4];
            float4 av2 = *(const float4*)&sap[2 * NDIM + k4];
            float4 av3 = *(const float4*)&sap[3 * NDIM + k4];
            float a0[4] = { av0.x, av0.y, av0.z, av0.w };
            float a1[4] = { av1.x, av1.y, av1.z, av1.w };
            float a2[4] = { av2.x, av2.y, av2.z, av2.w };
            float a3[4] = { av3.x, av3.y, av3.z, av3.w };
#pragma unroll
            for (int kk = 0; kk < 4; ++kk) {
                ulonglong2 wv = *(const ulonglong2*)&sW[(k4 + kk) * NDIM + qd];
                unsigned long long aa;
                aa = pk2f(a0[kk], a0[kk]);
                fma2(acc[0][0], aa, wv.x, acc[0][0]);
                fma2(acc[0][1], aa, wv.y, acc[0][1]);
                aa = pk2f(a1[kk], a1[kk]);
                fma2(acc[1][0], aa, wv.x, acc[1][0]);
                fma2(acc[1][1], aa, wv.y, acc[1][1]);
                aa = pk2f(a2[kk], a2[kk]);
                fma2(acc[2][0], aa, wv.x, acc[2][0]);
                fma2(acc[2][1], aa, wv.y, acc[2][1]);
                aa = pk2f(a3[kk], a3[kk]);
                fma2(acc[3][0], aa, wv.x, acc[3][0]);
                fma2(acc[3][1], aa, wv.y, acc[3][1]);
            }
        }
#pragma unroll
        for (int j = 0; j < 4; ++j) {
            int r = base + j;
            if (r >= n) break;
            unsigned long long m0, m1;
            add2(m0, acc[j][0], bb0);
            add2(m1, acc[j][1], bb1);
            float f0, f1, f2, f3;
            up2(f0, f1, m0);
            up2(f2, f3, m1);
            f0 = lrelu(f0); f1 = lrelu(f1); f2 = lrelu(f2); f3 = lrelu(f3);
            f0 += __shfl_xor_sync(0xffffffffu, f0, 16);
            f1 += __shfl_xor_sync(0xffffffffu, f1, 16);
            f2 += __shfl_xor_sync(0xffffffffu, f2, 16);
            f3 += __shfl_xor_sync(0xffffffffu, f3, 16);
            if (half == 0) {
                float4 ov = { f0, f1, f2, f3 };
                *(float4*)(out + (size_t)r * NDIM + qd) = ov;
            }
        }
        __syncwarp();
    }
}

// ---------------- launch ----------------
extern "C" void kernel_launch(void* const* d_in, const int* in_sizes, int n_in,
                              void* d_out, int out_size) {
    const float* ego   = (const float*)d_in[0];
    const float* rel   = (const float*)d_in[1];
    const int*   row1  = (const int*)d_in[2];
    const int*   col1  = (const int*)d_in[3];
    const float* vals1 = (const float*)d_in[4];
    const int*   row2  = (const int*)d_in[5];
    const int*   relix = (const int*)d_in[6];
    const float* vals2 = (const float*)d_in[7];
    const float* W1    = (const float*)d_in[8];
    const float* b1    = (const float*)d_in[9];
    const float* W2    = (const float*)d_in[10];
    const float* b2    = (const float*)d_in[11];
    float* out = (float*)d_out;

    int n = in_sizes[0] / NDIM;   // 100000
    int e = in_sizes[2];          // 3200000

    build_kernel<<<(e / 4 + 255) / 256, 256>>>(row1, col1, vals1, row2, relix, vals2, e);

    size_t smemBytes = (size_t)(4096 + 4096 + 2048 + 2048 + 2048) * sizeof(float); // 57344 B
    cudaFuncSetAttribute(fused_kernel, cudaFuncAttributeMaxDynamicSharedMemorySize,
                         (int)smemBytes);
    int smCount = 148;
    cudaDeviceGetAttribute(&smCount, cudaDevAttrMultiProcessorCount, 0);
    int blocksPerSM = 2;
    cudaOccupancyMaxActiveBlocksPerMultiprocessor(&blocksPerSM, fused_kernel, 256,
                                                  smemBytes);
    if (blocksPerSM < 1) blocksPerSM = 1;
    int grid = smCount * blocksPerSM;
    fused_kernel<<<grid, 256, smemBytes>>>(ego, rel, W1, b1, W2, b2, out, n);
}